// round 1
// baseline (speedup 1.0000x reference)
#include <cuda_runtime.h>

#define DIMV   512
#define NROWS  16384
#define KCODES 8192

#define BM 128
#define BN 128
#define BKT 16
#define TM 8
#define TN 8

// Scratch (device globals — no runtime allocation allowed)
__device__ float g_esq[KCODES];
__device__ unsigned long long g_best[NROWS];

// Monotonic packing of (score, idx): larger packed == better (higher score,
// then smaller index on exact float ties, matching jnp.argmax first-hit).
__device__ __forceinline__ unsigned long long pack_score(float s, int idx) {
    unsigned u = __float_as_uint(s);
    u = (u & 0x80000000u) ? ~u : (u | 0x80000000u);
    return ((unsigned long long)u << 32) | (unsigned)(KCODES - 1 - idx);
}

// Kernel 1: per-code squared norms + reset per-row best slots.
__global__ void vq_prep_kernel(const float* __restrict__ embed) {
    int b = blockIdx.x;                 // grid = NROWS blocks
    if (threadIdx.x == 0) g_best[b] = 0ULL;
    if (b < KCODES) {
        const float4* e = (const float4*)(embed + (size_t)b * DIMV);
        float s = 0.f;
        for (int t = threadIdx.x; t < DIMV / 4; t += blockDim.x) {
            float4 v = e[t];
            s += v.x * v.x + v.y * v.y + v.z * v.z + v.w * v.w;
        }
        __shared__ float red[4];
        #pragma unroll
        for (int o = 16; o > 0; o >>= 1) s += __shfl_down_sync(0xffffffffu, s, o);
        if ((threadIdx.x & 31) == 0) red[threadIdx.x >> 5] = s;
        __syncthreads();
        if (threadIdx.x == 0) g_esq[b] = red[0] + red[1] + red[2] + red[3];
    }
}

// Kernel 2: fused SGEMM (dot(x_row, embed_code)) + argmax epilogue.
// Block computes a BM x BN score tile over the full D=512 reduction,
// then atomically folds per-row best (score,idx) into g_best.
__global__ __launch_bounds__(256, 2)
void vq_main_kernel(const float* __restrict__ x, const float* __restrict__ embed) {
    __shared__ float As[BKT][BM];
    __shared__ float Bs[BKT][BN];
    __shared__ unsigned long long sbest[BM];

    const int rowBase = blockIdx.y * BM;
    const int colBase = blockIdx.x * BN;
    const int tid = threadIdx.x;
    const int tx = tid % (BN / TN);     // 0..15
    const int ty = tid / (BN / TN);     // 0..15

    float acc[TM][TN];
    #pragma unroll
    for (int i = 0; i < TM; i++)
        #pragma unroll
        for (int j = 0; j < TN; j++) acc[i][j] = 0.f;

    const int lr = tid >> 2;            // 0..63 (row within half-tile)
    const int lc = tid & 3;             // float4 column 0..3

    for (int d0 = 0; d0 < DIMV; d0 += BKT) {
        // Load + transpose x tile and embed tile into shared
        #pragma unroll
        for (int p = 0; p < 2; p++) {
            int r = lr + p * 64;
            float4 v = *(const float4*)(x + (size_t)(rowBase + r) * DIMV + d0 + lc * 4);
            As[lc * 4 + 0][r] = v.x; As[lc * 4 + 1][r] = v.y;
            As[lc * 4 + 2][r] = v.z; As[lc * 4 + 3][r] = v.w;
            float4 w = *(const float4*)(embed + (size_t)(colBase + r) * DIMV + d0 + lc * 4);
            Bs[lc * 4 + 0][r] = w.x; Bs[lc * 4 + 1][r] = w.y;
            Bs[lc * 4 + 2][r] = w.z; Bs[lc * 4 + 3][r] = w.w;
        }
        __syncthreads();

        #pragma unroll
        for (int k = 0; k < BKT; k++) {
            float rm[TM], rn[TN];
            *(float4*)&rm[0] = *(const float4*)&As[k][ty * TM];
            *(float4*)&rm[4] = *(const float4*)&As[k][ty * TM + 4];
            *(float4*)&rn[0] = *(const float4*)&Bs[k][tx * TN];
            *(float4*)&rn[4] = *(const float4*)&Bs[k][tx * TN + 4];
            #pragma unroll
            for (int i = 0; i < TM; i++)
                #pragma unroll
                for (int j = 0; j < TN; j++)
                    acc[i][j] = fmaf(rm[i], rn[j], acc[i][j]);
        }
        __syncthreads();
    }

    // Argmax epilogue: score = 2*dot - |e|^2
    for (int r = tid; r < BM; r += 256) sbest[r] = 0ULL;
    __syncthreads();

    float esq_r[TN];
    #pragma unroll
    for (int j = 0; j < TN; j++) esq_r[j] = g_esq[colBase + tx * TN + j];

    #pragma unroll
    for (int i = 0; i < TM; i++) {
        unsigned long long best = 0ULL;
        #pragma unroll
        for (int j = 0; j < TN; j++) {
            float score = 2.0f * acc[i][j] - esq_r[j];
            unsigned long long p = pack_score(score, colBase + tx * TN + j);
            best = (p > best) ? p : best;
        }
        atomicMax(&sbest[ty * TM + i], best);
    }
    __syncthreads();

    for (int r = tid; r < BM; r += 256) {
        unsigned long long b = sbest[r];
        if (b) atomicMax(&g_best[rowBase + r], b);
    }
}

// Kernel 3: gather quantize = embed[idx] and optionally write indices as float.
__global__ void vq_gather_kernel(const float* __restrict__ embed,
                                 float* __restrict__ out, int write_idx) {
    int row = blockIdx.x;
    unsigned long long p = g_best[row];
    int idx = KCODES - 1 - (int)(unsigned)(p & 0xFFFFFFFFu);
    const float4* src = (const float4*)(embed + (size_t)idx * DIMV);
    float4* dst = (float4*)(out + (size_t)row * DIMV);
    for (int t = threadIdx.x; t < DIMV / 4; t += blockDim.x) dst[t] = src[t];
    if (write_idx && threadIdx.x == 0)
        out[(size_t)NROWS * DIMV + row] = (float)idx;
}

extern "C" void kernel_launch(void* const* d_in, const int* in_sizes, int n_in,
                              void* d_out, int out_size) {
    const float* x     = (const float*)d_in[0];
    const float* embed = (const float*)d_in[1];
    float* out = (float*)d_out;

    vq_prep_kernel<<<NROWS, 128>>>(embed);

    dim3 grid(KCODES / BN, NROWS / BM);   // 64 x 128 blocks
    vq_main_kernel<<<grid, 256>>>(x, embed);

    int write_idx = (out_size >= NROWS * DIMV + NROWS) ? 1 : 0;
    vq_gather_kernel<<<NROWS, 128>>>(embed, out, write_idx);
}

// round 3
// speedup vs baseline: 6.8931x; 6.8931x over previous
#include <cuda_runtime.h>
#include <cuda_bf16.h>

#define DIMV   512
#define NROWS  16384
#define KCODES 8192

#define BM 128
#define BN 128
#define BK 64
#define NCHUNK (DIMV / BK)        // 8
#define NSEG  (KCODES / 32)       // 256 segments of 32 codes
#define CPR   (NSEG * 2)          // 512 candidate slots per row
#define EPSF  1.0f

// ---------------- device globals (no runtime allocation allowed) ----------
__device__ __align__(16) __nv_bfloat16 g_xb[(size_t)NROWS * DIMV];
__device__ __align__(16) __nv_bfloat16 g_eb[(size_t)KCODES * DIMV];
__device__ float g_esq[KCODES];
__device__ unsigned long long g_cand[(size_t)NROWS * CPR];

// ---------------- packing: monotonic (score, smaller-idx-wins) ------------
__device__ __forceinline__ unsigned long long pack_score(float s, int idx) {
    unsigned u = __float_as_uint(s);
    u = (u & 0x80000000u) ? ~u : (u | 0x80000000u);
    return ((unsigned long long)u << 32) | (unsigned)(KCODES - 1 - idx);
}
__device__ __forceinline__ float unpack_score(unsigned long long p) {
    unsigned u = (unsigned)(p >> 32);
    u = (u & 0x80000000u) ? (u ^ 0x80000000u) : ~u;
    return __uint_as_float(u);
}
__device__ __forceinline__ int unpack_idx(unsigned long long p) {
    return KCODES - 1 - (int)(unsigned)(p & 0xFFFFFFFFu);
}
__device__ __forceinline__ void merge2(unsigned long long& a, unsigned long long& b,
                                       unsigned long long p) {
    if (p > a) { b = a; a = p; } else if (p > b) { b = p; }
}

__device__ __forceinline__ unsigned smem_u32(const void* p) {
    unsigned a;
    asm("{ .reg .u64 t; cvta.to.shared.u64 t, %1; cvt.u32.u64 %0, t; }"
        : "=r"(a) : "l"(p));
    return a;
}

// ---------------- kernel 1: bf16 conversion + |e|^2 ------------------------
__global__ void vq_prep(const float* __restrict__ x, const float* __restrict__ embed) {
    int b = blockIdx.x, tid = threadIdx.x;   // NROWS blocks x 128 threads
    float4 v = ((const float4*)(x + (size_t)b * DIMV))[tid];
    __nv_bfloat162 p0, p1;
    p0.x = __float2bfloat16(v.x); p0.y = __float2bfloat16(v.y);
    p1.x = __float2bfloat16(v.z); p1.y = __float2bfloat16(v.w);
    uint2 pk = make_uint2(*(unsigned*)&p0, *(unsigned*)&p1);
    *(uint2*)(g_xb + (size_t)b * DIMV + tid * 4) = pk;

    if (b < KCODES) {
        float4 e = ((const float4*)(embed + (size_t)b * DIMV))[tid];
        __nv_bfloat162 q0, q1;
        q0.x = __float2bfloat16(e.x); q0.y = __float2bfloat16(e.y);
        q1.x = __float2bfloat16(e.z); q1.y = __float2bfloat16(e.w);
        uint2 qk = make_uint2(*(unsigned*)&q0, *(unsigned*)&q1);
        *(uint2*)(g_eb + (size_t)b * DIMV + tid * 4) = qk;

        float s = e.x * e.x + e.y * e.y + e.z * e.z + e.w * e.w;
        #pragma unroll
        for (int o = 16; o > 0; o >>= 1) s += __shfl_down_sync(0xffffffffu, s, o);
        __shared__ float red[4];
        if ((tid & 31) == 0) red[tid >> 5] = s;
        __syncthreads();
        if (tid == 0) g_esq[b] = red[0] + red[1] + red[2] + red[3];
    }
}

// ---------------- kernel 2: bf16 HMMA GEMM + top-2-per-segment epilogue ----
// CTA: 128(M) x 128(N), BK=64, 256 threads; warp grid 2(m) x 4(n), warp tile 64x32.
__global__ __launch_bounds__(256, 2)
void vq_gemm() {
    extern __shared__ char smem[];                // A0,B0,A1,B1: 4 x 16KB
    __shared__ float s_esq[BN];

    const int tid = threadIdx.x, lane = tid & 31, wid = tid >> 5;
    const int wm = wid >> 2, wn = wid & 3;
    const int rowBase = blockIdx.y * BM;
    const int colBase = blockIdx.x * BN;
    const unsigned sb = smem_u32(smem);

    if (tid < BN) s_esq[tid] = g_esq[colBase + tid];

    float acc[4][4][4];
    #pragma unroll
    for (int mt = 0; mt < 4; mt++)
        #pragma unroll
        for (int nt = 0; nt < 4; nt++)
            #pragma unroll
            for (int q = 0; q < 4; q++) acc[mt][nt][q] = 0.f;

    // cp.async tile loader: 128 rows x 8 chunks(16B) per operand, swizzled
    #define ISSUE_CHUNK(c) do {                                              \
        const int _buf = (c) & 1;                                            \
        const unsigned _aB = sb + _buf * 32768u;                             \
        const unsigned _bB = _aB + 16384u;                                   \
        const __nv_bfloat16* _xp = g_xb + (size_t)rowBase * DIMV + (c) * BK; \
        const __nv_bfloat16* _ep = g_eb + (size_t)colBase * DIMV + (c) * BK; \
        _Pragma("unroll")                                                    \
        for (int _it = 0; _it < 4; _it++) {                                  \
            int _u = tid + _it * 256;                                        \
            int _r = _u >> 3, _c = _u & 7;                                   \
            unsigned _off = _r * 128 + (((_c ^ (_r & 7))) << 4);             \
            asm volatile("cp.async.cg.shared.global [%0], [%1], 16;"         \
                :: "r"(_aB + _off), "l"(_xp + (size_t)_r * DIMV + _c * 8));  \
            asm volatile("cp.async.cg.shared.global [%0], [%1], 16;"         \
                :: "r"(_bB + _off), "l"(_ep + (size_t)_r * DIMV + _c * 8));  \
        }                                                                    \
        asm volatile("cp.async.commit_group;");                              \
    } while (0)

    ISSUE_CHUNK(0);

    #pragma unroll 1
    for (int c = 0; c < NCHUNK; c++) {
        if (c < NCHUNK - 1) {
            ISSUE_CHUNK(c + 1);
            asm volatile("cp.async.wait_group 1;");
        } else {
            asm volatile("cp.async.wait_group 0;");
        }
        __syncthreads();

        const unsigned aBase = sb + (c & 1) * 32768u;
        const unsigned bBase = aBase + 16384u;

        #pragma unroll
        for (int ks = 0; ks < 4; ks++) {
            unsigned af[4][4], bf[4][2];
            #pragma unroll
            for (int mt = 0; mt < 4; mt++) {
                int rA = wm * 64 + mt * 16 + (lane & 15);
                int cA = ks * 2 + (lane >> 4);
                unsigned addr = aBase + rA * 128 + (((cA ^ (rA & 7))) << 4);
                asm volatile("ldmatrix.sync.aligned.m8n8.x4.shared.b16 "
                             "{%0,%1,%2,%3}, [%4];"
                             : "=r"(af[mt][0]), "=r"(af[mt][1]),
                               "=r"(af[mt][2]), "=r"(af[mt][3]) : "r"(addr));
            }
            #pragma unroll
            for (int nt = 0; nt < 4; nt++) {
                int rB = wn * 32 + nt * 8 + (lane & 7);
                int cB = ks * 2 + ((lane >> 3) & 1);
                unsigned addr = bBase + rB * 128 + (((cB ^ (rB & 7))) << 4);
                asm volatile("ldmatrix.sync.aligned.m8n8.x2.shared.b16 "
                             "{%0,%1}, [%2];"
                             : "=r"(bf[nt][0]), "=r"(bf[nt][1]) : "r"(addr));
            }
            #pragma unroll
            for (int mt = 0; mt < 4; mt++)
                #pragma unroll
                for (int nt = 0; nt < 4; nt++)
                    asm volatile(
                        "mma.sync.aligned.m16n8k16.row.col.f32.bf16.bf16.f32 "
                        "{%0,%1,%2,%3}, {%4,%5,%6,%7}, {%8,%9}, {%0,%1,%2,%3};"
                        : "+f"(acc[mt][nt][0]), "+f"(acc[mt][nt][1]),
                          "+f"(acc[mt][nt][2]), "+f"(acc[mt][nt][3])
                        : "r"(af[mt][0]), "r"(af[mt][1]),
                          "r"(af[mt][2]), "r"(af[mt][3]),
                          "r"(bf[nt][0]), "r"(bf[nt][1]));
        }
        __syncthreads();
    }

    // ---- epilogue: per-(row, 32-col segment) top-2 -------------------------
    const int gq = lane >> 2;          // row group 0..7
    const int qt = lane & 3;           // col quad 0..3
    float esqv[4][2];
    #pragma unroll
    for (int nt = 0; nt < 4; nt++) {
        int cl = wn * 32 + nt * 8 + qt * 2;
        esqv[nt][0] = s_esq[cl];
        esqv[nt][1] = s_esq[cl + 1];
    }
    const int seg = (colBase + wn * 32) >> 5;

    #pragma unroll
    for (int mt = 0; mt < 4; mt++) {
        int r0 = rowBase + wm * 64 + mt * 16 + gq;
        int r1 = r0 + 8;
        unsigned long long a0 = 0, b0 = 0, a1 = 0, b1 = 0;
        #pragma unroll
        for (int nt = 0; nt < 4; nt++) {
            int cg = colBase + wn * 32 + nt * 8 + qt * 2;
            merge2(a0, b0, pack_score(2.f * acc[mt][nt][0] - esqv[nt][0], cg));
            merge2(a0, b0, pack_score(2.f * acc[mt][nt][1] - esqv[nt][1], cg + 1));
            merge2(a1, b1, pack_score(2.f * acc[mt][nt][2] - esqv[nt][0], cg));
            merge2(a1, b1, pack_score(2.f * acc[mt][nt][3] - esqv[nt][1], cg + 1));
        }
        #pragma unroll
        for (int off = 1; off <= 2; off <<= 1) {
            unsigned long long xa0 = __shfl_xor_sync(0xffffffffu, a0, off);
            unsigned long long xb0 = __shfl_xor_sync(0xffffffffu, b0, off);
            unsigned long long xa1 = __shfl_xor_sync(0xffffffffu, a1, off);
            unsigned long long xb1 = __shfl_xor_sync(0xffffffffu, b1, off);
            merge2(a0, b0, xa0); merge2(a0, b0, xb0);
            merge2(a1, b1, xa1); merge2(a1, b1, xb1);
        }
        if (qt == 0) {
            g_cand[(size_t)r0 * CPR + seg * 2]     = a0;
            g_cand[(size_t)r0 * CPR + seg * 2 + 1] = b0;
            g_cand[(size_t)r1 * CPR + seg * 2]     = a1;
            g_cand[(size_t)r1 * CPR + seg * 2 + 1] = b1;
        }
    }
}

// ---------------- kernel 3: exact fp32 rescore + gather --------------------
__global__ void vq_rescore(const float* __restrict__ x, const float* __restrict__ embed,
                           float* __restrict__ out, int write_idx) {
    const int row = blockIdx.x, tid = threadIdx.x;   // 128 threads
    const int wid = tid >> 5, lid = tid & 31;
    __shared__ unsigned long long s_max4[4];
    __shared__ int s_cnt;
    __shared__ int s_idx[64];
    __shared__ float s_red[4];
    __shared__ unsigned long long s_win;
    if (tid == 0) s_cnt = 0;

    const unsigned long long* cd = g_cand + (size_t)row * CPR;
    unsigned long long m = 0;
    #pragma unroll
    for (int i = tid; i < CPR; i += 128) m = max(m, cd[i]);
    #pragma unroll
    for (int o = 16; o > 0; o >>= 1)
        m = max(m, __shfl_down_sync(0xffffffffu, m, o));
    if (lid == 0) s_max4[wid] = m;
    __syncthreads();
    m = max(max(s_max4[0], s_max4[1]), max(s_max4[2], s_max4[3]));
    const float thr = unpack_score(m) - EPSF;

    for (int i = tid; i < CPR; i += 128) {
        unsigned long long p = cd[i];
        if (unpack_score(p) >= thr) {
            int k = atomicAdd(&s_cnt, 1);
            if (k < 64) s_idx[k] = unpack_idx(p);
        }
    }
    __syncthreads();
    const int cnt = min(s_cnt, 64);

    const float4 xv = ((const float4*)(x + (size_t)row * DIMV))[tid];
    unsigned long long best = 0ULL;
    for (int c = 0; c < cnt; c++) {
        const int idx = s_idx[c];
        float4 ev = ((const float4*)(embed + (size_t)idx * DIMV))[tid];
        float d = xv.x * ev.x + xv.y * ev.y + xv.z * ev.z + xv.w * ev.w;
        #pragma unroll
        for (int o = 16; o > 0; o >>= 1) d += __shfl_down_sync(0xffffffffu, d, o);
        if (lid == 0) s_red[wid] = d;
        __syncthreads();
        if (tid == 0) {
            float dot = s_red[0] + s_red[1] + s_red[2] + s_red[3];
            unsigned long long p = pack_score(2.0f * dot - g_esq[idx], idx);
            if (p > best) best = p;
        }
        __syncthreads();
    }
    if (tid == 0) s_win = best;
    __syncthreads();

    const int widx = unpack_idx(s_win);
    float4 ev = ((const float4*)(embed + (size_t)widx * DIMV))[tid];
    ((float4*)(out + (size_t)row * DIMV))[tid] = ev;
    if (write_idx && tid == 0)
        out[(size_t)NROWS * DIMV + row] = (float)widx;
}

// ---------------- launch ----------------------------------------------------
extern "C" void kernel_launch(void* const* d_in, const int* in_sizes, int n_in,
                              void* d_out, int out_size) {
    const float* x     = (const float*)d_in[0];
    const float* embed = (const float*)d_in[1];
    float* out = (float*)d_out;

    cudaFuncSetAttribute(vq_gemm, cudaFuncAttributeMaxDynamicSharedMemorySize, 65536);

    vq_prep<<<NROWS, 128>>>(x, embed);

    dim3 grid(KCODES / BN, NROWS / BM);   // 64 x 128
    vq_gemm<<<grid, 256, 65536>>>();

    int write_idx = (out_size >= NROWS * DIMV + NROWS) ? 1 : 0;
    vq_rescore<<<NROWS, 128>>>(x, embed, out, write_idx);
}